// round 5
// baseline (speedup 1.0000x reference)
#include <cuda_runtime.h>

#define BATCH 256
#define NTOK 256
#define DIMC 256
#define NHEADS 8
#define HD 32
#define NGROUP 64
#define LPOS 961   // (2*16-1)*(2*16-1)

// ---------------- scratch (static device globals; no runtime allocation) ----
__device__ float g_qh[(size_t)BATCH * NHEADS * NTOK * HD];
__device__ float g_kh[(size_t)BATCH * NHEADS * NTOK * HD];
__device__ float g_vh[(size_t)BATCH * NHEADS * NTOK * HD];
__device__ float g_x [(size_t)BATCH * NTOK * DIMC];
__device__ float g_pos[LPOS * NHEADS];

// ---------------- fast exp: FFMA-only (avoids MUFU bottleneck) --------------
__device__ __forceinline__ float fast_exp(float x) {
    x = fmaxf(x, -80.0f);
    float y = x * 1.4426950408889634f;          // x * log2(e)
    float t = y + 12582912.0f;                  // round-to-nearest via magic
    float n = t - 12582912.0f;
    float f = y - n;                            // f in [-0.5, 0.5]
    int   ni = (int)n;
    float r = 1.3333558146e-3f;                 // 2^f Taylor (exp(f*ln2))
    r = fmaf(r, f, 9.6181291918e-3f);
    r = fmaf(r, f, 5.5504108665e-2f);
    r = fmaf(r, f, 2.4022650696e-1f);
    r = fmaf(r, f, 6.9314718056e-1f);
    r = fmaf(r, f, 1.0f);
    return r * __int_as_float((ni + 127) << 23);
}

// ---------------- DynamicPosBias MLP (961 positions, PD=16, out NH=8) -------
__device__ __forceinline__ void lnorm16(float* x, const float* g, const float* b) {
    float m = 0.f;
    #pragma unroll
    for (int i = 0; i < 16; i++) m += x[i];
    m *= (1.0f / 16.0f);
    float v = 0.f;
    #pragma unroll
    for (int i = 0; i < 16; i++) { float d = x[i] - m; v += d * d; }
    v *= (1.0f / 16.0f);
    float r = rsqrtf(v + 1e-5f);
    #pragma unroll
    for (int i = 0; i < 16; i++) x[i] = (x[i] - m) * r * g[i] + b[i];
}

__global__ void pos_mlp_kernel(
    const float* __restrict__ pp_w, const float* __restrict__ pp_b,
    const float* __restrict__ ln1_g, const float* __restrict__ ln1_b,
    const float* __restrict__ l1_w, const float* __restrict__ l1_b,
    const float* __restrict__ ln2_g, const float* __restrict__ ln2_b,
    const float* __restrict__ l2_w, const float* __restrict__ l2_b,
    const float* __restrict__ ln3_g, const float* __restrict__ ln3_b,
    const float* __restrict__ l3_w, const float* __restrict__ l3_b)
{
    int l = blockIdx.x * blockDim.x + threadIdx.x;
    if (l >= LPOS) return;
    float b0 = (float)(l / 31) - 15.0f;   // bh
    float b1 = (float)(l % 31) - 15.0f;   // bw
    float x[16], y[16];
    #pragma unroll
    for (int p = 0; p < 16; p++)
        x[p] = fmaf(b0, pp_w[p * 2 + 0], fmaf(b1, pp_w[p * 2 + 1], pp_b[p]));
    lnorm16(x, ln1_g, ln1_b);
    #pragma unroll
    for (int p = 0; p < 16; p++) {
        float s = l1_b[p];
        #pragma unroll
        for (int q = 0; q < 16; q++) s = fmaf(fmaxf(x[q], 0.f), l1_w[p * 16 + q], s);
        y[p] = s;
    }
    lnorm16(y, ln2_g, ln2_b);
    #pragma unroll
    for (int p = 0; p < 16; p++) {
        float s = l2_b[p];
        #pragma unroll
        for (int q = 0; q < 16; q++) s = fmaf(fmaxf(y[q], 0.f), l2_w[p * 16 + q], s);
        x[p] = s;
    }
    lnorm16(x, ln3_g, ln3_b);
    #pragma unroll
    for (int h = 0; h < NHEADS; h++) {
        float s = l3_b[h];
        #pragma unroll
        for (int q = 0; q < 16; q++) s = fmaf(fmaxf(x[q], 0.f), l3_w[h * 16 + q], s);
        g_pos[l * NHEADS + h] = s;
    }
}

// ---------------- generic SGEMM: C[r][c] = sum_k A[r,k]*W[c,k] + bias[c] ----
// MODE 0: Nout=256, write qh layout (b, h, t, d)
// MODE 1: Nout=512, write kh/vh layouts
// MODE 2: Nout=256, read g_x, write d_out row-major
template<int NOUT, int MODE>
__global__ __launch_bounds__(256)
void gemm_kernel(const float* __restrict__ A_in,
                 const float* __restrict__ Wt,
                 const float* __restrict__ bias,
                 float* __restrict__ Oout)
{
    const int K = 256, BM = 128, BN = 64, BK = 16;
    __shared__ float As[BK][BM];
    __shared__ float Ws[BK][BN];
    const float* A = (MODE == 2) ? g_x : A_in;
    int tid = threadIdx.x;
    int rowBase = blockIdx.x * BM;
    int colBase = blockIdx.y * BN;
    int tx = tid & 15, ty = tid >> 4;
    float acc[8][4];
    #pragma unroll
    for (int i = 0; i < 8; i++)
        #pragma unroll
        for (int j = 0; j < 4; j++) acc[i][j] = 0.f;

    for (int k0 = 0; k0 < K; k0 += BK) {
        #pragma unroll
        for (int i = 0; i < 2; i++) {
            int f = tid + i * 256;            // float4 index, 512 total
            int r = f >> 2, kq = (f & 3) * 4;
            float4 v = *(const float4*)&A[(size_t)(rowBase + r) * K + k0 + kq];
            As[kq + 0][r] = v.x; As[kq + 1][r] = v.y;
            As[kq + 2][r] = v.z; As[kq + 3][r] = v.w;
        }
        {
            int c = tid >> 2, kq = (tid & 3) * 4;
            float4 v = *(const float4*)&Wt[(size_t)(colBase + c) * K + k0 + kq];
            Ws[kq + 0][c] = v.x; Ws[kq + 1][c] = v.y;
            Ws[kq + 2][c] = v.z; Ws[kq + 3][c] = v.w;
        }
        __syncthreads();
        #pragma unroll
        for (int k = 0; k < BK; k++) {
            float4 a0 = *(const float4*)&As[k][ty * 8];
            float4 a1 = *(const float4*)&As[k][ty * 8 + 4];
            float4 w0 = *(const float4*)&Ws[k][tx * 4];
            float a[8] = {a0.x, a0.y, a0.z, a0.w, a1.x, a1.y, a1.z, a1.w};
            float w[4] = {w0.x, w0.y, w0.z, w0.w};
            #pragma unroll
            for (int i = 0; i < 8; i++)
                #pragma unroll
                for (int j = 0; j < 4; j++)
                    acc[i][j] = fmaf(a[i], w[j], acc[i][j]);
        }
        __syncthreads();
    }

    #pragma unroll
    for (int j = 0; j < 4; j++) {
        int c = colBase + tx * 4 + j;
        float bv = bias[c];
        #pragma unroll
        for (int i = 0; i < 8; i++) {
            int r = rowBase + ty * 8 + i;
            float val = acc[i][j] + bv;
            if (MODE == 2) {
                Oout[(size_t)r * 256 + c] = val;
            } else {
                int b = r >> 8, t = r & 255;
                if (MODE == 0) {
                    int h = c / HD, d = c % HD;
                    g_qh[((((size_t)b * NHEADS + h) * NTOK + t) * HD) + d] = val;
                } else {
                    int half = c >> 8, cc = c & 255;
                    int h = cc / HD, d = cc % HD;
                    size_t off = (((size_t)b * NHEADS + h) * NTOK + t) * HD + d;
                    if (half) g_vh[off] = val; else g_kh[off] = val;
                }
            }
        }
    }
}

// ---------------- fused attention: per (b,h) CTA, online softmax ------------
#define SMEM_ATTN ((2 * NTOK * HD + LPOS + 3) * sizeof(float))

__global__ __launch_bounds__(256)
void attn_kernel(const float* __restrict__ mask)
{
    extern __shared__ float sm[];
    float* k_s   = sm;                       // 8192
    float* v_s   = sm + NTOK * HD;           // 8192
    float* pos_s = sm + 2 * NTOK * HD;       // 961

    int bh = blockIdx.x;
    int b = bh >> 3, h = bh & 7;
    int tid = threadIdx.x;

    const float4* kb = (const float4*)(g_kh + (size_t)bh * NTOK * HD);
    const float4* vb = (const float4*)(g_vh + (size_t)bh * NTOK * HD);
    #pragma unroll
    for (int i = tid; i < NTOK * HD / 4; i += 256) {
        ((float4*)k_s)[i] = kb[i];
        ((float4*)v_s)[i] = vb[i];
    }
    for (int i = tid; i < LPOS; i += 256) pos_s[i] = g_pos[i * NHEADS + h];
    __syncthreads();

    int t = tid;
    const float scale = 0.17677669529663687f;   // 1/sqrt(32)
    float qr[HD];
    {
        const float4* qrow = (const float4*)(g_qh + ((size_t)bh * NTOK + t) * HD);
        #pragma unroll
        for (int i = 0; i < HD / 4; i++) {
            float4 v4 = qrow[i];
            qr[4 * i + 0] = v4.x * scale; qr[4 * i + 1] = v4.y * scale;
            qr[4 * i + 2] = v4.z * scale; qr[4 * i + 3] = v4.w * scale;
        }
    }
    const float* mrow = mask + ((size_t)(b & (NGROUP - 1)) * NTOK + t) * NTOK;
    int th = t >> 4, tw = t & 15;

    float mx = -1e30f, ssum = 0.f;
    float acc[HD];
    #pragma unroll
    for (int d = 0; d < HD; d++) acc[d] = 0.f;

    for (int m = 0; m < NTOK; m++) {
        const float4* kv = (const float4*)(k_s + m * HD);
        float s0 = 0.f, s1 = 0.f, s2 = 0.f, s3 = 0.f;
        #pragma unroll
        for (int i = 0; i < HD / 16; i++) {
            float4 a = kv[4 * i + 0], b4 = kv[4 * i + 1], c4 = kv[4 * i + 2], d4 = kv[4 * i + 3];
            s0 = fmaf(qr[16 * i + 0], a.x, s0);  s1 = fmaf(qr[16 * i + 1], a.y, s1);
            s2 = fmaf(qr[16 * i + 2], a.z, s2);  s3 = fmaf(qr[16 * i + 3], a.w, s3);
            s0 = fmaf(qr[16 * i + 4], b4.x, s0); s1 = fmaf(qr[16 * i + 5], b4.y, s1);
            s2 = fmaf(qr[16 * i + 6], b4.z, s2); s3 = fmaf(qr[16 * i + 7], b4.w, s3);
            s0 = fmaf(qr[16 * i + 8], c4.x, s0); s1 = fmaf(qr[16 * i + 9], c4.y, s1);
            s2 = fmaf(qr[16 * i + 10], c4.z, s2); s3 = fmaf(qr[16 * i + 11], c4.w, s3);
            s0 = fmaf(qr[16 * i + 12], d4.x, s0); s1 = fmaf(qr[16 * i + 13], d4.y, s1);
            s2 = fmaf(qr[16 * i + 14], d4.z, s2); s3 = fmaf(qr[16 * i + 15], d4.w, s3);
        }
        float s = (s0 + s1) + (s2 + s3);
        int mh = m >> 4, mw = m & 15;
        int idx = (th - mh + 15) * 31 + (tw - mw + 15);
        s += pos_s[idx] + mrow[m];

        if (s > mx) {                       // rare rescale path
            float corr = fast_exp(mx - s);
            ssum *= corr;
            #pragma unroll
            for (int d = 0; d < HD; d++) acc[d] *= corr;
            mx = s;
        }
        float p = fast_exp(s - mx);
        ssum += p;
        const float4* vv = (const float4*)(v_s + m * HD);
        #pragma unroll
        for (int i = 0; i < HD / 4; i++) {
            float4 v4 = vv[i];
            acc[4 * i + 0] = fmaf(p, v4.x, acc[4 * i + 0]);
            acc[4 * i + 1] = fmaf(p, v4.y, acc[4 * i + 1]);
            acc[4 * i + 2] = fmaf(p, v4.z, acc[4 * i + 2]);
            acc[4 * i + 3] = fmaf(p, v4.w, acc[4 * i + 3]);
        }
    }

    float inv = 1.0f / ssum;
    float* orow = g_x + ((size_t)b * NTOK + t) * DIMC + h * HD;
    #pragma unroll
    for (int i = 0; i < HD / 4; i++) {
        float4 o;
        o.x = acc[4 * i + 0] * inv; o.y = acc[4 * i + 1] * inv;
        o.z = acc[4 * i + 2] * inv; o.w = acc[4 * i + 3] * inv;
        ((float4*)orow)[i] = o;
    }
}

// ---------------- launch ----------------------------------------------------
extern "C" void kernel_launch(void* const* d_in, const int* in_sizes, int n_in,
                              void* d_out, int out_size)
{
    const float* q      = (const float*)d_in[0];
    const float* k      = (const float*)d_in[1];
    const float* mask   = (const float*)d_in[2];
    const float* q_w    = (const float*)d_in[3];
    const float* q_b    = (const float*)d_in[4];
    const float* kv_w   = (const float*)d_in[5];
    const float* kv_b   = (const float*)d_in[6];
    const float* proj_w = (const float*)d_in[7];
    const float* proj_b = (const float*)d_in[8];
    const float* pp_w   = (const float*)d_in[9];
    const float* pp_b   = (const float*)d_in[10];
    const float* ln1_g  = (const float*)d_in[11];
    const float* ln1_b  = (const float*)d_in[12];
    const float* l1_w   = (const float*)d_in[13];
    const float* l1_b   = (const float*)d_in[14];
    const float* ln2_g  = (const float*)d_in[15];
    const float* ln2_b  = (const float*)d_in[16];
    const float* l2_w   = (const float*)d_in[17];
    const float* l2_b   = (const float*)d_in[18];
    const float* ln3_g  = (const float*)d_in[19];
    const float* ln3_b  = (const float*)d_in[20];
    const float* l3_w   = (const float*)d_in[21];
    const float* l3_b   = (const float*)d_in[22];
    float* out = (float*)d_out;

    static int smem_set = 0;
    if (!smem_set) {
        cudaFuncSetAttribute(attn_kernel, cudaFuncAttributeMaxDynamicSharedMemorySize,
                             (int)SMEM_ATTN);
        smem_set = 1;
    }

    pos_mlp_kernel<<<1, 992>>>(pp_w, pp_b, ln1_g, ln1_b, l1_w, l1_b,
                               ln2_g, ln2_b, l2_w, l2_b, ln3_g, ln3_b, l3_w, l3_b);

    // Q projection: (65536,256) x (256,256)^T
    gemm_kernel<256, 0><<<dim3(512, 4), 256>>>(q, q_w, q_b, nullptr);
    // KV projection: (65536,256) x (512,256)^T
    gemm_kernel<512, 1><<<dim3(512, 8), 256>>>(k, kv_w, kv_b, nullptr);
    // fused attention
    attn_kernel<<<BATCH * NHEADS, 256, SMEM_ATTN>>>(mask);
    // output projection
    gemm_kernel<256, 2><<<dim3(512, 4), 256>>>(nullptr, proj_w, proj_b, out);
}

// round 7
// speedup vs baseline: 1.1532x; 1.1532x over previous
#include <cuda_runtime.h>

#define BATCH 256
#define NTOK 256
#define DIMC 256
#define NHEADS 8
#define HD 32
#define NGROUP 64
#define LPOS 961   // (2*16-1)*(2*16-1)
#define TM 32      // mask tile (m-dimension)

// ---------------- scratch (static device globals; no runtime allocation) ----
__device__ float g_qh[(size_t)BATCH * NHEADS * NTOK * HD];
__device__ float g_kh[(size_t)BATCH * NHEADS * NTOK * HD];
__device__ float g_vh[(size_t)BATCH * NHEADS * NTOK * HD];
__device__ float g_x [(size_t)BATCH * NTOK * DIMC];
__device__ float g_pos[LPOS * NHEADS];

// ---------------- fast exp: FFMA-only (avoids MUFU bottleneck) --------------
__device__ __forceinline__ float fast_exp(float x) {
    x = fmaxf(x, -80.0f);
    float y = x * 1.4426950408889634f;          // x * log2(e)
    float t = y + 12582912.0f;                  // round-to-nearest via magic
    float n = t - 12582912.0f;
    float f = y - n;                            // f in [-0.5, 0.5]
    int   ni = (int)n;
    float r = 1.3333558146e-3f;                 // 2^f Taylor (exp(f*ln2))
    r = fmaf(r, f, 9.6181291918e-3f);
    r = fmaf(r, f, 5.5504108665e-2f);
    r = fmaf(r, f, 2.4022650696e-1f);
    r = fmaf(r, f, 6.9314718056e-1f);
    r = fmaf(r, f, 1.0f);
    return r * __int_as_float((ni + 127) << 23);
}

// ---------------- DynamicPosBias MLP (961 positions, PD=16, out NH=8) -------
__device__ __forceinline__ void lnorm16(float* x, const float* g, const float* b) {
    float m = 0.f;
    #pragma unroll
    for (int i = 0; i < 16; i++) m += x[i];
    m *= (1.0f / 16.0f);
    float v = 0.f;
    #pragma unroll
    for (int i = 0; i < 16; i++) { float d = x[i] - m; v += d * d; }
    v *= (1.0f / 16.0f);
    float r = rsqrtf(v + 1e-5f);
    #pragma unroll
    for (int i = 0; i < 16; i++) x[i] = (x[i] - m) * r * g[i] + b[i];
}

__global__ void pos_mlp_kernel(
    const float* __restrict__ pp_w, const float* __restrict__ pp_b,
    const float* __restrict__ ln1_g, const float* __restrict__ ln1_b,
    const float* __restrict__ l1_w, const float* __restrict__ l1_b,
    const float* __restrict__ ln2_g, const float* __restrict__ ln2_b,
    const float* __restrict__ l2_w, const float* __restrict__ l2_b,
    const float* __restrict__ ln3_g, const float* __restrict__ ln3_b,
    const float* __restrict__ l3_w, const float* __restrict__ l3_b)
{
    int l = blockIdx.x * blockDim.x + threadIdx.x;
    if (l >= LPOS) return;
    float b0 = (float)(l / 31) - 15.0f;   // bh
    float b1 = (float)(l % 31) - 15.0f;   // bw
    float x[16], y[16];
    #pragma unroll
    for (int p = 0; p < 16; p++)
        x[p] = fmaf(b0, pp_w[p * 2 + 0], fmaf(b1, pp_w[p * 2 + 1], pp_b[p]));
    lnorm16(x, ln1_g, ln1_b);
    #pragma unroll
    for (int p = 0; p < 16; p++) {
        float s = l1_b[p];
        #pragma unroll
        for (int q = 0; q < 16; q++) s = fmaf(fmaxf(x[q], 0.f), l1_w[p * 16 + q], s);
        y[p] = s;
    }
    lnorm16(y, ln2_g, ln2_b);
    #pragma unroll
    for (int p = 0; p < 16; p++) {
        float s = l2_b[p];
        #pragma unroll
        for (int q = 0; q < 16; q++) s = fmaf(fmaxf(y[q], 0.f), l2_w[p * 16 + q], s);
        x[p] = s;
    }
    lnorm16(x, ln3_g, ln3_b);
    #pragma unroll
    for (int h = 0; h < NHEADS; h++) {
        float s = l3_b[h];
        #pragma unroll
        for (int q = 0; q < 16; q++) s = fmaf(fmaxf(x[q], 0.f), l3_w[h * 16 + q], s);
        g_pos[l * NHEADS + h] = s;
    }
}

// ---------------- generic SGEMM: C[r][c] = sum_k A[r,k]*W[c,k] + bias[c] ----
// MODE 0: Nout=256, write qh layout (b, h, t, d)
// MODE 1: Nout=512, write kh/vh layouts
// MODE 2: Nout=256, read g_x, write d_out row-major
template<int NOUT, int MODE>
__global__ __launch_bounds__(256)
void gemm_kernel(const float* __restrict__ A_in,
                 const float* __restrict__ Wt,
                 const float* __restrict__ bias,
                 float* __restrict__ Oout)
{
    const int K = 256, BM = 128, BN = 64, BK = 16;
    __shared__ float As[BK][BM];
    __shared__ float Ws[BK][BN];
    const float* A = (MODE == 2) ? g_x : A_in;
    int tid = threadIdx.x;
    int rowBase = blockIdx.x * BM;
    int colBase = blockIdx.y * BN;
    int tx = tid & 15, ty = tid >> 4;
    float acc[8][4];
    #pragma unroll
    for (int i = 0; i < 8; i++)
        #pragma unroll
        for (int j = 0; j < 4; j++) acc[i][j] = 0.f;

    for (int k0 = 0; k0 < K; k0 += BK) {
        #pragma unroll
        for (int i = 0; i < 2; i++) {
            int f = tid + i * 256;            // float4 index, 512 total
            int r = f >> 2, kq = (f & 3) * 4;
            float4 v = *(const float4*)&A[(size_t)(rowBase + r) * K + k0 + kq];
            As[kq + 0][r] = v.x; As[kq + 1][r] = v.y;
            As[kq + 2][r] = v.z; As[kq + 3][r] = v.w;
        }
        {
            int c = tid >> 2, kq = (tid & 3) * 4;
            float4 v = *(const float4*)&Wt[(size_t)(colBase + c) * K + k0 + kq];
            Ws[kq + 0][c] = v.x; Ws[kq + 1][c] = v.y;
            Ws[kq + 2][c] = v.z; Ws[kq + 3][c] = v.w;
        }
        __syncthreads();
        #pragma unroll
        for (int k = 0; k < BK; k++) {
            float4 a0 = *(const float4*)&As[k][ty * 8];
            float4 a1 = *(const float4*)&As[k][ty * 8 + 4];
            float4 w0 = *(const float4*)&Ws[k][tx * 4];
            float a[8] = {a0.x, a0.y, a0.z, a0.w, a1.x, a1.y, a1.z, a1.w};
            float w[4] = {w0.x, w0.y, w0.z, w0.w};
            #pragma unroll
            for (int i = 0; i < 8; i++)
                #pragma unroll
                for (int j = 0; j < 4; j++)
                    acc[i][j] = fmaf(a[i], w[j], acc[i][j]);
        }
        __syncthreads();
    }

    #pragma unroll
    for (int j = 0; j < 4; j++) {
        int c = colBase + tx * 4 + j;
        float bv = bias[c];
        #pragma unroll
        for (int i = 0; i < 8; i++) {
            int r = rowBase + ty * 8 + i;
            float val = acc[i][j] + bv;
            if (MODE == 2) {
                Oout[(size_t)r * 256 + c] = val;
            } else {
                int b = r >> 8, t = r & 255;
                if (MODE == 0) {
                    int h = c / HD, d = c % HD;
                    g_qh[((((size_t)b * NHEADS + h) * NTOK + t) * HD) + d] = val;
                } else {
                    int half = c >> 8, cc = c & 255;
                    int h = cc / HD, d = cc % HD;
                    size_t off = (((size_t)b * NHEADS + h) * NTOK + t) * HD + d;
                    if (half) g_vh[off] = val; else g_kh[off] = val;
                }
            }
        }
    }
}

// ---------------- fused attention: per (b,h) CTA, online softmax ------------
// smem: K (8192f) + V (8192f) + pos (961f) + mask tile (256 * 33 f)
#define MT_STRIDE (TM + 1)
#define SMEM_ATTN ((2 * NTOK * HD + LPOS + 3 + NTOK * MT_STRIDE) * sizeof(float))

__global__ __launch_bounds__(256)
void attn_kernel(const float* __restrict__ mask)
{
    extern __shared__ float sm[];
    float* k_s   = sm;                            // 8192
    float* v_s   = sm + NTOK * HD;                // 8192
    float* pos_s = sm + 2 * NTOK * HD;            // 961
    float* mtile = sm + 2 * NTOK * HD + LPOS + 3; // 256*33

    int bh = blockIdx.x;
    int b = bh >> 3, h = bh & 7;
    int tid = threadIdx.x;

    const float4* kb = (const float4*)(g_kh + (size_t)bh * NTOK * HD);
    const float4* vb = (const float4*)(g_vh + (size_t)bh * NTOK * HD);
    #pragma unroll
    for (int i = tid; i < NTOK * HD / 4; i += 256) {
        ((float4*)k_s)[i] = kb[i];
        ((float4*)v_s)[i] = vb[i];
    }
    for (int i = tid; i < LPOS; i += 256) pos_s[i] = g_pos[i * NHEADS + h];
    __syncthreads();

    int t = tid;
    const float scale = 0.17677669529663687f;   // 1/sqrt(32)
    float qr[HD];
    {
        const float4* qrow = (const float4*)(g_qh + ((size_t)bh * NTOK + t) * HD);
        #pragma unroll
        for (int i = 0; i < HD / 4; i++) {
            float4 v4 = qrow[i];
            qr[4 * i + 0] = v4.x * scale; qr[4 * i + 1] = v4.y * scale;
            qr[4 * i + 2] = v4.z * scale; qr[4 * i + 3] = v4.w * scale;
        }
    }
    const float* mbase = mask + (size_t)(b & (NGROUP - 1)) * NTOK * NTOK;
    int th = t >> 4, tw = t & 15;

    float mx = -1e30f, ssum = 0.f;
    float acc[HD];
    #pragma unroll
    for (int d = 0; d < HD; d++) acc[d] = 0.f;

    for (int m0 = 0; m0 < NTOK; m0 += TM) {
        // ---- cooperative, coalesced mask tile load: mask[g, 0:256, m0:m0+TM]
        __syncthreads();
        #pragma unroll
        for (int i = 0; i < (NTOK * TM / 4) / 256; i++) {
            int f = i * 256 + tid;            // float4 index
            int r = f >> 3;                   // token row (TM/4 = 8 quads/row)
            int q = f & 7;                    // quad within row
            float4 v4 = *(const float4*)&mbase[(size_t)r * NTOK + m0 + 4 * q];
            float* dst = &mtile[r * MT_STRIDE + 4 * q];
            dst[0] = v4.x; dst[1] = v4.y; dst[2] = v4.z; dst[3] = v4.w;
        }
        __syncthreads();

        const float* mrow_s = &mtile[t * MT_STRIDE];

        #pragma unroll 2
        for (int mm = 0; mm < TM; mm++) {
            int m = m0 + mm;
            const float4* kv = (const float4*)(k_s + m * HD);
            float s0 = 0.f, s1 = 0.f, s2 = 0.f, s3 = 0.f;
            #pragma unroll
            for (int i = 0; i < HD / 16; i++) {
                float4 a = kv[4 * i + 0], b4 = kv[4 * i + 1], c4 = kv[4 * i + 2], d4 = kv[4 * i + 3];
                s0 = fmaf(qr[16 * i + 0], a.x, s0);  s1 = fmaf(qr[16 * i + 1], a.y, s1);
                s2 = fmaf(qr[16 * i + 2], a.z, s2);  s3 = fmaf(qr[16 * i + 3], a.w, s3);
                s0 = fmaf(qr[16 * i + 4], b4.x, s0); s1 = fmaf(qr[16 * i + 5], b4.y, s1);
                s2 = fmaf(qr[16 * i + 6], b4.z, s2); s3 = fmaf(qr[16 * i + 7], b4.w, s3);
                s0 = fmaf(qr[16 * i + 8], c4.x, s0); s1 = fmaf(qr[16 * i + 9], c4.y, s1);
                s2 = fmaf(qr[16 * i + 10], c4.z, s2); s3 = fmaf(qr[16 * i + 11], c4.w, s3);
                s0 = fmaf(qr[16 * i + 12], d4.x, s0); s1 = fmaf(qr[16 * i + 13], d4.y, s1);
                s2 = fmaf(qr[16 * i + 14], d4.z, s2); s3 = fmaf(qr[16 * i + 15], d4.w, s3);
            }
            float s = (s0 + s1) + (s2 + s3);
            int mh = m >> 4, mw = m & 15;
            int idx = (th - mh + 15) * 31 + (tw - mw + 15);
            s += pos_s[idx] + mrow_s[mm];

            if (s > mx) {                       // rare rescale path
                float corr = fast_exp(mx - s);
                ssum *= corr;
                #pragma unroll
                for (int d = 0; d < HD; d++) acc[d] *= corr;
                mx = s;
            }
            float p = fast_exp(s - mx);
            ssum += p;
            const float4* vv = (const float4*)(v_s + m * HD);
            #pragma unroll
            for (int i = 0; i < HD / 4; i++) {
                float4 v4 = vv[i];
                acc[4 * i + 0] = fmaf(p, v4.x, acc[4 * i + 0]);
                acc[4 * i + 1] = fmaf(p, v4.y, acc[4 * i + 1]);
                acc[4 * i + 2] = fmaf(p, v4.z, acc[4 * i + 2]);
                acc[4 * i + 3] = fmaf(p, v4.w, acc[4 * i + 3]);
            }
        }
    }

    float inv = 1.0f / ssum;
    float* orow = g_x + ((size_t)b * NTOK + t) * DIMC + h * HD;
    #pragma unroll
    for (int i = 0; i < HD / 4; i++) {
        float4 o;
        o.x = acc[4 * i + 0] * inv; o.y = acc[4 * i + 1] * inv;
        o.z = acc[4 * i + 2] * inv; o.w = acc[4 * i + 3] * inv;
        ((float4*)orow)[i] = o;
    }
}

// ---------------- launch ----------------------------------------------------
extern "C" void kernel_launch(void* const* d_in, const int* in_sizes, int n_in,
                              void* d_out, int out_size)
{
    const float* q      = (const float*)d_in[0];
    const float* k      = (const float*)d_in[1];
    const float* mask   = (const float*)d_in[2];
    const float* q_w    = (const float*)d_in[3];
    const float* q_b    = (const float*)d_in[4];
    const float* kv_w   = (const float*)d_in[5];
    const float* kv_b   = (const float*)d_in[6];
    const float* proj_w = (const float*)d_in[7];
    const float* proj_b = (const float*)d_in[8];
    const float* pp_w   = (const float*)d_in[9];
    const float* pp_b   = (const float*)d_in[10];
    const float* ln1_g  = (const float*)d_in[11];
    const float* ln1_b  = (const float*)d_in[12];
    const float* l1_w   = (const float*)d_in[13];
    const float* l1_b   = (const float*)d_in[14];
    const float* ln2_g  = (const float*)d_in[15];
    const float* ln2_b  = (const float*)d_in[16];
    const float* l2_w   = (const float*)d_in[17];
    const float* l2_b   = (const float*)d_in[18];
    const float* ln3_g  = (const float*)d_in[19];
    const float* ln3_b  = (const float*)d_in[20];
    const float* l3_w   = (const float*)d_in[21];
    const float* l3_b   = (const float*)d_in[22];
    float* out = (float*)d_out;

    static int smem_set = 0;
    if (!smem_set) {
        cudaFuncSetAttribute(attn_kernel, cudaFuncAttributeMaxDynamicSharedMemorySize,
                             (int)SMEM_ATTN);
        smem_set = 1;
    }

    pos_mlp_kernel<<<1, 992>>>(pp_w, pp_b, ln1_g, ln1_b, l1_w, l1_b,
                               ln2_g, ln2_b, l2_w, l2_b, ln3_g, ln3_b, l3_w, l3_b);

    // Q projection: (65536,256) x (256,256)^T
    gemm_kernel<256, 0><<<dim3(512, 4), 256>>>(q, q_w, q_b, nullptr);
    // KV projection: (65536,256) x (512,256)^T
    gemm_kernel<512, 1><<<dim3(512, 8), 256>>>(k, kv_w, kv_b, nullptr);
    // fused attention
    attn_kernel<<<BATCH * NHEADS, 256, SMEM_ATTN>>>(mask);
    // output projection
    gemm_kernel<256, 2><<<dim3(512, 4), 256>>>(nullptr, proj_w, proj_b, out);
}